// round 9
// baseline (speedup 1.0000x reference)
#include <cuda_runtime.h>
#include <cstdint>

#define Nn   8192
#define Ee   262144
#define Tt   2048
#define NMAT 128          // matvec blocks (64 rows / 64 cols each)
#define NBLK (NMAT + 1)   // + 1 LSTM block
#define NTHR 512

// ---- scratch (device globals; no allocation allowed) ----
__device__ float g_v[Nn];        // xTB - x
__device__ float g_x1[Nn];       // edge scatter result
__device__ float g_x2[Nn];       // W3@(W2@v+b2)+b3 (seeded with b3, atomic-accumulated)
__device__ int   g_done;         // matvec blocks finished

// dynamic smem:
//   matvec blocks: s_v[8192] + s_x21[64]
//   LSTM block   : s_cur[2056] + s_h[16384] + red[17]
#define SMEM_BYTES ((2056 + 16384 + 17) * 4)

__device__ __forceinline__ float tanhap(float x) {
    float y;
    asm("tanh.approx.f32 %0, %1;" : "=f"(y) : "f"(x));
    return y;
}

// ---------------------------------------------------------------------------
// K0: init — g_x1 = 0, g_x2 = b3 (atomic accumulation base), v = xTB - x
// ---------------------------------------------------------------------------
__global__ void gl_init(const float* __restrict__ x, const float* __restrict__ xTB,
                        const float* __restrict__ b3) {
    int i = blockIdx.x * blockDim.x + threadIdx.x;
    if (i < Nn) {
        g_v[i]  = xTB[i] - x[i];
        g_x1[i] = 0.f;
        g_x2[i] = b3[i];
    }
    if (i == 0) g_done = 0;
}

// ---------------------------------------------------------------------------
// K1: mega kernel (barrier-free matvec chain + LSTM block)
// ---------------------------------------------------------------------------
__global__ void __launch_bounds__(NTHR, 1)
gl_main(const float* __restrict__ x,   const float* __restrict__ cur,
        const int*   __restrict__ ei,  const float* __restrict__ att,
        const float* __restrict__ W2,  const float* __restrict__ b2,
        const float* __restrict__ W3,
        const float* __restrict__ Wih, const float* __restrict__ Whh,
        const float* __restrict__ bih, const float* __restrict__ bhh,
        const float* __restrict__ W1,  const float* __restrict__ b1,
        const float* __restrict__ x30, float* __restrict__ out) {
    extern __shared__ float smem[];
    const int lane = threadIdx.x & 31;
    const int warp = threadIdx.x >> 5;

    if (blockIdx.x < NMAT) {
        // ================= matvec / scatter block =================
        float4* sv    = (float4*)smem;          // v staged: 8192 floats
        float*  s_x21 = smem + Nn;              // this block's 64 x21 values

        {   // stage v into smem
            const float4* gv = (const float4*)g_v;
            for (int i = threadIdx.x; i < Nn / 4; i += NTHR) sv[i] = gv[i];
        }
        {   // edge scatter
            int tid  = blockIdx.x * NTHR + threadIdx.x;
            int nthr = NMAT * NTHR;
            for (int e = tid; e < Ee; e += nthr) {
                int s = ei[e];
                int d = ei[Ee + e];
                float m = (__ldg(x + s) - __ldg(x + d)) * __ldg(att + e);
                atomicAdd(&g_x1[d], m);
            }
        }
        __syncthreads();

        // ---- mv1: rows [64b, 64b+64), warp-per-row, 16-deep batched loads ----
        const int row0 = blockIdx.x * 64;
        for (int r = warp; r < 64; r += NTHR / 32) {
            int row = row0 + r;
            const float4* wr = (const float4*)(W2 + (size_t)row * Nn) + lane;
            float acc0 = 0.f, acc1 = 0.f;
            #pragma unroll 1
            for (int c = 0; c < 4; ++c) {
                float4 w[16];
                #pragma unroll
                for (int k = 0; k < 16; ++k)
                    w[k] = __ldg(wr + (c * 16 + k) * 32);
                #pragma unroll
                for (int k = 0; k < 16; ++k) {
                    float4 u = sv[lane + (c * 16 + k) * 32];
                    acc0 = fmaf(w[k].x, u.x, acc0);
                    acc1 = fmaf(w[k].y, u.y, acc1);
                    acc0 = fmaf(w[k].z, u.z, acc0);
                    acc1 = fmaf(w[k].w, u.w, acc1);
                }
            }
            float acc = acc0 + acc1;
            #pragma unroll
            for (int o = 16; o; o >>= 1) acc += __shfl_down_sync(0xffffffffu, acc, o);
            if (lane == 0) s_x21[r] = acc + b2[row];
        }
        __syncthreads();

        // ---- mv2: column slice W3[:, 64b:64b+64) @ s_x21, row-per-lane ----
        const float4* sx = (const float4*)s_x21;
        const int c4 = blockIdx.x * 16;
        #pragma unroll 1
        for (int p = 0; p < Nn / NTHR; ++p) {
            int row = p * NTHR + threadIdx.x;
            const float4* wr = (const float4*)(W3 + (size_t)row * Nn) + c4;
            float a0 = 0.f, a1 = 0.f;
            #pragma unroll
            for (int k = 0; k < 16; ++k) {
                float4 w = __ldg(wr + k);
                float4 u = sx[k];
                a0 = fmaf(w.x, u.x, a0);
                a1 = fmaf(w.y, u.y, a1);
                a0 = fmaf(w.z, u.z, a0);
                a1 = fmaf(w.w, u.w, a1);
            }
            atomicAdd(&g_x2[row], a0 + a1);
        }

        __syncthreads();
        if (threadIdx.x == 0) {
            __threadfence();
            atomicAdd(&g_done, 1);
        }
    } else {
        // ================= LSTM block =================
        float* s_cur = smem;                        // [2056] (padded for prefetch)
        float* s_h   = smem + 2056;                 // [16384]: h history (off-chain)
        float* s_red = smem + 2056 + 16384;         // [16]
        float* s_x3  = s_red + 16;

        for (int i = threadIdx.x; i < Tt; i += NTHR) s_cur[i] = cur[i];
        if (threadIdx.x < 8) s_cur[Tt + threadIdx.x] = 0.f;
        __syncthreads();

        if (warp == 0) {
            // gate-per-lane: lane = gt*8 + u
            // sigmoid gates (gt 0,1,3) via 0.5*tanh(z/2)+0.5; gate 2 tanh
            const int u  = lane & 7;
            const int gt = lane >> 3;
            const bool sig = (gt != 2);
            const bool is_o = (gt == 3);            // o-lanes own h (register-resident)
            const float wscale = sig ? 0.5f : 1.0f;
            const float sca = sig ? 0.5f : 1.0f;
            const float scb = sig ? 0.5f : 0.0f;

            float w0 = wscale * Whh[lane * 8 + 0];
            float w1 = wscale * Whh[lane * 8 + 1];
            float w2 = wscale * Whh[lane * 8 + 2];
            float w3 = wscale * Whh[lane * 8 + 3];
            float w4 = wscale * Whh[lane * 8 + 4];
            float w5 = wscale * Whh[lane * 8 + 5];
            float w6 = wscale * Whh[lane * 8 + 6];
            float w7 = wscale * Whh[lane * 8 + 7];
            float a  = wscale * Wih[lane];
            float bb = wscale * (bih[lane] + bhh[lane]);

            float c = 0.f, h = 0.f;                 // h meaningful in o-lanes
            float xt = s_cur[0];
            float* shp = s_h + u;                   // history store (off-chain)

            #pragma unroll 8
            for (int t = 0; t < Tt; t++) {
                // broadcast h(t-1) from o-lanes 24..31 (register-resident)
                float h0 = __shfl_sync(0xffffffffu, h, 24);
                float h1 = __shfl_sync(0xffffffffu, h, 25);
                float h2 = __shfl_sync(0xffffffffu, h, 26);
                float h3 = __shfl_sync(0xffffffffu, h, 27);
                float h4 = __shfl_sync(0xffffffffu, h, 28);
                float h5 = __shfl_sync(0xffffffffu, h, 29);
                float h6 = __shfl_sync(0xffffffffu, h, 30);
                float h7 = __shfl_sync(0xffffffffu, h, 31);

                float pre = fmaf(a, xt, bb);
                float xn  = s_cur[t + 1];           // prefetch (off-chain)

                // 4-accumulator tree dot (depth 2 FMA + 2 ADD)
                float a0 = fmaf(w0, h0, pre);
                float a1 = w2 * h2;
                float a2 = w4 * h4;
                float a3 = w6 * h6;
                a0 = fmaf(w1, h1, a0);
                a1 = fmaf(w3, h3, a1);
                a2 = fmaf(w5, h5, a2);
                a3 = fmaf(w7, h7, a3);
                float z = (a0 + a1) + (a2 + a3);

                float v = fmaf(tanhap(z), sca, scb);   // gate value (gt,u)

                // gather i, f, g (o is local to lanes 24-31)
                float si = __shfl_sync(0xffffffffu, v, u);
                float sf = __shfl_sync(0xffffffffu, v, 8 + u);
                float tg = __shfl_sync(0xffffffffu, v, 16 + u);

                c = fmaf(sf, c, si * tg);
                h = v * tanhap(c);                  // valid h only in o-lanes

                if (is_o) shp[t * 8] = h;           // history, off the chain
                xt = xn;
            }
        }
        __syncthreads();   // s_h visible block-wide

        // x3 scalar = W1 · hs_flat + b1
        float part = 0.f;
        for (int k = threadIdx.x; k < Tt * 8; k += NTHR)
            part = fmaf(__ldg(W1 + k), s_h[k], part);
        #pragma unroll
        for (int o = 16; o; o >>= 1) part += __shfl_down_sync(0xffffffffu, part, o);
        if (lane == 0) s_red[warp] = part;
        __syncthreads();
        if (threadIdx.x == 0) {
            float s = 0.f;
            #pragma unroll
            for (int w = 0; w < NTHR / 32; w++) s += s_red[w];
            *s_x3 = s + b1[0];
            while (atomicAdd(&g_done, 0) < NMAT) {}  // wait for matvec blocks
            __threadfence();
        }
        __syncthreads();

        float x3 = *s_x3;
        for (int i = threadIdx.x; i < Nn; i += NTHR)
            out[i] = x[i] + g_x1[i] + g_x2[i] + x3 * x30[i];
    }
}

// ---------------------------------------------------------------------------
extern "C" void kernel_launch(void* const* d_in, const int* in_sizes, int n_in,
                              void* d_out, int out_size) {
    const float* x   = (const float*)d_in[0];
    const float* xTB = (const float*)d_in[1];
    const float* cur = (const float*)d_in[2];
    const int*   ei  = (const int*)  d_in[3];
    const float* att = (const float*)d_in[4];
    const float* W2  = (const float*)d_in[5];
    const float* b2  = (const float*)d_in[6];
    const float* W3  = (const float*)d_in[7];
    const float* b3  = (const float*)d_in[8];
    const float* Wih = (const float*)d_in[9];
    const float* Whh = (const float*)d_in[10];
    const float* bih = (const float*)d_in[11];
    const float* bhh = (const float*)d_in[12];
    const float* W1  = (const float*)d_in[13];
    const float* b1  = (const float*)d_in[14];
    const float* x30 = (const float*)d_in[15];
    float* out = (float*)d_out;

    cudaFuncSetAttribute(gl_main, cudaFuncAttributeMaxDynamicSharedMemorySize,
                         SMEM_BYTES);

    gl_init<<<(Nn + 255) / 256, 256>>>(x, xTB, b3);
    gl_main<<<NBLK, NTHR, SMEM_BYTES>>>(x, cur, ei, att, W2, b2, W3,
                                        Wih, Whh, bih, bhh, W1, b1, x30, out);
}

// round 10
// speedup vs baseline: 1.3439x; 1.3439x over previous
#include <cuda_runtime.h>
#include <cstdint>

#define Nn    8192
#define Ee    262144
#define Tt    2048
#define NMAT  128         // matvec blocks (64 rows / 64 cols each)
#define NBLK  (NMAT + 1)  // + 1 LSTM block
#define NTHR  512
#define NCH   64          // time chunks
#define STEPS 32          // steps per chunk
#define NSWEEP 3

// ---- scratch (device globals; no allocation allowed) ----
__device__ float g_v[Nn];
__device__ float g_x1[Nn];
__device__ float g_x2[Nn];       // seeded with b3, atomic-accumulated
__device__ int   g_done;

// LSTM-block smem (floats):
//   s_cur[2048] | s_h[16384] | bndh0[520] bndc0[520] bndh1[520] bndc1[520] | red[17]
#define BSZ  ((NCH + 1) * 8)     // 520
#define SMEM_FLOATS (2048 + 16384 + 4 * BSZ + 17)
#define SMEM_BYTES (SMEM_FLOATS * 4)

__device__ __forceinline__ float tanhap(float x) {
    float y;
    asm("tanh.approx.f32 %0, %1;" : "=f"(y) : "f"(x));
    return y;
}

// ---------------------------------------------------------------------------
__global__ void gl_init(const float* __restrict__ x, const float* __restrict__ xTB,
                        const float* __restrict__ b3) {
    int i = blockIdx.x * blockDim.x + threadIdx.x;
    if (i < Nn) {
        g_v[i]  = xTB[i] - x[i];
        g_x1[i] = 0.f;
        g_x2[i] = b3[i];
    }
    if (i == 0) g_done = 0;
}

// ---------------------------------------------------------------------------
__global__ void __launch_bounds__(NTHR, 1)
gl_main(const float* __restrict__ x,   const float* __restrict__ cur,
        const int*   __restrict__ ei,  const float* __restrict__ att,
        const float* __restrict__ W2,  const float* __restrict__ b2,
        const float* __restrict__ W3,
        const float* __restrict__ Wih, const float* __restrict__ Whh,
        const float* __restrict__ bih, const float* __restrict__ bhh,
        const float* __restrict__ W1,  const float* __restrict__ b1,
        const float* __restrict__ x30, float* __restrict__ out) {
    extern __shared__ float smem[];
    const int lane = threadIdx.x & 31;
    const int warp = threadIdx.x >> 5;

    if (blockIdx.x < NMAT) {
        // ================= matvec / scatter block (R8, unchanged) ============
        float4* sv    = (float4*)smem;
        float*  s_x21 = smem + Nn;

        {
            const float4* gv = (const float4*)g_v;
            for (int i = threadIdx.x; i < Nn / 4; i += NTHR) sv[i] = gv[i];
        }
        {
            int tid  = blockIdx.x * NTHR + threadIdx.x;
            int nthr = NMAT * NTHR;
            for (int e = tid; e < Ee; e += nthr) {
                int s = ei[e];
                int d = ei[Ee + e];
                float m = (__ldg(x + s) - __ldg(x + d)) * __ldg(att + e);
                atomicAdd(&g_x1[d], m);
            }
        }
        __syncthreads();

        const int row0 = blockIdx.x * 64;
        for (int r = warp; r < 64; r += NTHR / 32) {
            int row = row0 + r;
            const float4* wr = (const float4*)(W2 + (size_t)row * Nn) + lane;
            float acc0 = 0.f, acc1 = 0.f;
            #pragma unroll 1
            for (int c = 0; c < 4; ++c) {
                float4 w[16];
                #pragma unroll
                for (int k = 0; k < 16; ++k)
                    w[k] = __ldg(wr + (c * 16 + k) * 32);
                #pragma unroll
                for (int k = 0; k < 16; ++k) {
                    float4 u = sv[lane + (c * 16 + k) * 32];
                    acc0 = fmaf(w[k].x, u.x, acc0);
                    acc1 = fmaf(w[k].y, u.y, acc1);
                    acc0 = fmaf(w[k].z, u.z, acc0);
                    acc1 = fmaf(w[k].w, u.w, acc1);
                }
            }
            float acc = acc0 + acc1;
            #pragma unroll
            for (int o = 16; o; o >>= 1) acc += __shfl_down_sync(0xffffffffu, acc, o);
            if (lane == 0) s_x21[r] = acc + b2[row];
        }
        __syncthreads();

        const float4* sx = (const float4*)s_x21;
        const int c4 = blockIdx.x * 16;
        #pragma unroll 1
        for (int p = 0; p < Nn / NTHR; ++p) {
            int row = p * NTHR + threadIdx.x;
            const float4* wr = (const float4*)(W3 + (size_t)row * Nn) + c4;
            float a0 = 0.f, a1 = 0.f;
            #pragma unroll
            for (int k = 0; k < 16; ++k) {
                float4 w = __ldg(wr + k);
                float4 u = sx[k];
                a0 = fmaf(w.x, u.x, a0);
                a1 = fmaf(w.y, u.y, a1);
                a0 = fmaf(w.z, u.z, a0);
                a1 = fmaf(w.w, u.w, a1);
            }
            atomicAdd(&g_x2[row], a0 + a1);
        }

        __syncthreads();
        if (threadIdx.x == 0) {
            __threadfence();
            atomicAdd(&g_done, 1);
        }
    } else {
        // ================= LSTM block: parallel-in-time =================
        float* s_cur = smem;                        // [2048]
        float* s_h   = smem + 2048;                 // [16384] full h history
        float* bndh0 = smem + 2048 + 16384;         // [520]
        float* bndc0 = bndh0 + BSZ;
        float* bndh1 = bndc0 + BSZ;
        float* bndc1 = bndh1 + BSZ;
        float* s_red = bndc1 + BSZ;                 // [16]
        float* s_x3  = s_red + 16;

        for (int i = threadIdx.x; i < Tt; i += NTHR) s_cur[i] = cur[i];
        for (int i = threadIdx.x; i < BSZ; i += NTHR) {
            bndh0[i] = 0.f; bndc0[i] = 0.f;
            bndh1[i] = 0.f; bndc1[i] = 0.f;
        }
        __syncthreads();

        // unit-per-lane, all-gates: lane = 8*sub + u; warp handles 4 chunks
        const int u    = lane & 7;
        const int base = lane & 24;                 // shfl group base
        const int q    = warp * 4 + (lane >> 3);    // chunk id, 0..63
        const int t0   = q * STEPS;

        // per-lane weights for unit u, all 4 gates (sigmoid gates pre-scaled 0.5)
        float wi[8], wf[8], wg[8], wo[8];
        #pragma unroll
        for (int j = 0; j < 8; j++) {
            wi[j] = 0.5f * Whh[(u)      * 8 + j];
            wf[j] = 0.5f * Whh[(8 + u)  * 8 + j];
            wg[j] =        Whh[(16 + u) * 8 + j];
            wo[j] = 0.5f * Whh[(24 + u) * 8 + j];
        }
        const float ai = 0.5f * Wih[u],      bi2 = 0.5f * (bih[u]      + bhh[u]);
        const float af = 0.5f * Wih[8 + u],  bf2 = 0.5f * (bih[8 + u]  + bhh[8 + u]);
        const float ag =        Wih[16 + u], bg2 =        (bih[16 + u] + bhh[16 + u]);
        const float ao = 0.5f * Wih[24 + u], bo2 = 0.5f * (bih[24 + u] + bhh[24 + u]);

        #pragma unroll 1
        for (int sweep = 0; sweep < NSWEEP; sweep++) {
            const float* bh_in  = (sweep & 1) ? bndh1 : bndh0;
            const float* bc_in  = (sweep & 1) ? bndc1 : bndc0;
            float* bh_out = (sweep & 1) ? bndh0 : bndh1;
            float* bc_out = (sweep & 1) ? bndc0 : bndc1;

            float h = bh_in[q * 8 + u];     // own unit's boundary h
            float c = bc_in[q * 8 + u];

            #pragma unroll 4
            for (int s = 0; s < STEPS; s++) {
                int t = t0 + s;
                // broadcast h(t-1) within the 8-lane chunk group
                float h0 = __shfl_sync(0xffffffffu, h, base + 0);
                float h1 = __shfl_sync(0xffffffffu, h, base + 1);
                float h2 = __shfl_sync(0xffffffffu, h, base + 2);
                float h3 = __shfl_sync(0xffffffffu, h, base + 3);
                float h4 = __shfl_sync(0xffffffffu, h, base + 4);
                float h5 = __shfl_sync(0xffffffffu, h, base + 5);
                float h6 = __shfl_sync(0xffffffffu, h, base + 6);
                float h7 = __shfl_sync(0xffffffffu, h, base + 7);

                float xt = s_cur[t];
                float zi = fmaf(ai, xt, bi2);
                float zf = fmaf(af, xt, bf2);
                float zg = fmaf(ag, xt, bg2);
                float zo = fmaf(ao, xt, bo2);

                zi = fmaf(wi[0], h0, zi); zf = fmaf(wf[0], h0, zf);
                zg = fmaf(wg[0], h0, zg); zo = fmaf(wo[0], h0, zo);
                zi = fmaf(wi[1], h1, zi); zf = fmaf(wf[1], h1, zf);
                zg = fmaf(wg[1], h1, zg); zo = fmaf(wo[1], h1, zo);
                zi = fmaf(wi[2], h2, zi); zf = fmaf(wf[2], h2, zf);
                zg = fmaf(wg[2], h2, zg); zo = fmaf(wo[2], h2, zo);
                zi = fmaf(wi[3], h3, zi); zf = fmaf(wf[3], h3, zf);
                zg = fmaf(wg[3], h3, zg); zo = fmaf(wo[3], h3, zo);
                zi = fmaf(wi[4], h4, zi); zf = fmaf(wf[4], h4, zf);
                zg = fmaf(wg[4], h4, zg); zo = fmaf(wo[4], h4, zo);
                zi = fmaf(wi[5], h5, zi); zf = fmaf(wf[5], h5, zf);
                zg = fmaf(wg[5], h5, zg); zo = fmaf(wo[5], h5, zo);
                zi = fmaf(wi[6], h6, zi); zf = fmaf(wf[6], h6, zf);
                zg = fmaf(wg[6], h6, zg); zo = fmaf(wo[6], h6, zo);
                zi = fmaf(wi[7], h7, zi); zf = fmaf(wf[7], h7, zf);
                zg = fmaf(wg[7], h7, zg); zo = fmaf(wo[7], h7, zo);

                float si = fmaf(tanhap(zi), 0.5f, 0.5f);
                float sf = fmaf(tanhap(zf), 0.5f, 0.5f);
                float tg = tanhap(zg);
                float so = fmaf(tanhap(zo), 0.5f, 0.5f);

                c = fmaf(sf, c, si * tg);
                h = so * tanhap(c);

                s_h[t * 8 + u] = h;          // full history (last sweep wins)
            }

            // publish chunk-final state as next chunk's boundary (next sweep)
            bh_out[(q + 1) * 8 + u] = h;
            bc_out[(q + 1) * 8 + u] = c;
            __syncthreads();
        }

        // x3 scalar = W1 · hs_flat + b1
        float part = 0.f;
        for (int k = threadIdx.x; k < Tt * 8; k += NTHR)
            part = fmaf(__ldg(W1 + k), s_h[k], part);
        #pragma unroll
        for (int o = 16; o; o >>= 1) part += __shfl_down_sync(0xffffffffu, part, o);
        if (lane == 0) s_red[warp] = part;
        __syncthreads();
        if (threadIdx.x == 0) {
            float s = 0.f;
            #pragma unroll
            for (int w = 0; w < NTHR / 32; w++) s += s_red[w];
            *s_x3 = s + b1[0];
            while (atomicAdd(&g_done, 0) < NMAT) {}
            __threadfence();
        }
        __syncthreads();

        float x3 = *s_x3;
        for (int i = threadIdx.x; i < Nn; i += NTHR)
            out[i] = x[i] + g_x1[i] + g_x2[i] + x3 * x30[i];
    }
}

// ---------------------------------------------------------------------------
extern "C" void kernel_launch(void* const* d_in, const int* in_sizes, int n_in,
                              void* d_out, int out_size) {
    const float* x   = (const float*)d_in[0];
    const float* xTB = (const float*)d_in[1];
    const float* cur = (const float*)d_in[2];
    const int*   ei  = (const int*)  d_in[3];
    const float* att = (const float*)d_in[4];
    const float* W2  = (const float*)d_in[5];
    const float* b2  = (const float*)d_in[6];
    const float* W3  = (const float*)d_in[7];
    const float* b3  = (const float*)d_in[8];
    const float* Wih = (const float*)d_in[9];
    const float* Whh = (const float*)d_in[10];
    const float* bih = (const float*)d_in[11];
    const float* bhh = (const float*)d_in[12];
    const float* W1  = (const float*)d_in[13];
    const float* b1  = (const float*)d_in[14];
    const float* x30 = (const float*)d_in[15];
    float* out = (float*)d_out;

    cudaFuncSetAttribute(gl_main, cudaFuncAttributeMaxDynamicSharedMemorySize,
                         SMEM_BYTES);

    gl_init<<<(Nn + 255) / 256, 256>>>(x, xTB, b3);
    gl_main<<<NBLK, NTHR, SMEM_BYTES>>>(x, cur, ei, att, W2, b2, W3,
                                        Wih, Whh, bih, bhh, W1, b1, x30, out);
}

// round 11
// speedup vs baseline: 1.6742x; 1.2458x over previous
#include <cuda_runtime.h>
#include <cstdint>

#define Nn    8192
#define Ee    262144
#define Tt    2048
#define NMAT  151
#define NBLK  (NMAT + 1)  // + 1 LSTM block
#define NTHR  512
#define NCH   64          // time chunks
#define STEPS 32          // steps per chunk
#define NSWEEP 3

// ---- scratch (device globals; no allocation allowed) ----
__device__ float g_v[Nn];
__device__ float g_x1[Nn];
__device__ float g_x21[Nn];
__device__ float g_x2[Nn];
__device__ int   g_bar1;
__device__ int   g_done;

// LSTM-block smem (floats):
//   s_cur[2048] | s_h[16384] | bndh0[520] bndc0[520] bndh1[520] bndc1[520] | red[17]
#define BSZ  ((NCH + 1) * 8)
#define SMEM_FLOATS (2048 + 16384 + 4 * BSZ + 17)
#define SMEM_BYTES (SMEM_FLOATS * 4)

__device__ __forceinline__ float tanhap(float x) {
    float y;
    asm("tanh.approx.f32 %0, %1;" : "=f"(y) : "f"(x));
    return y;
}

// ---------------------------------------------------------------------------
__global__ void gl_init(const float* __restrict__ x, const float* __restrict__ xTB) {
    int i = blockIdx.x * blockDim.x + threadIdx.x;
    if (i < Nn) {
        g_v[i]  = xTB[i] - x[i];
        g_x1[i] = 0.f;
    }
    if (i == 0) { g_bar1 = 0; g_done = 0; }
}

// warp-per-row matvec, smem input vector, 16-deep front-batched W loads
__device__ __forceinline__ void matvec_rows16(const float* __restrict__ W,
                                              const float4* __restrict__ sv,
                                              const float* __restrict__ b,
                                              float* __restrict__ vout,
                                              int gw, int nw, int lane) {
    for (int row = gw; row < Nn; row += nw) {
        const float4* wr = (const float4*)(W + (size_t)row * Nn) + lane;
        float acc0 = 0.f, acc1 = 0.f;
        #pragma unroll 1
        for (int c = 0; c < 4; ++c) {
            float4 w[16];
            #pragma unroll
            for (int k = 0; k < 16; ++k)
                w[k] = __ldg(wr + (c * 16 + k) * 32);
            #pragma unroll
            for (int k = 0; k < 16; ++k) {
                float4 u = sv[lane + (c * 16 + k) * 32];
                acc0 = fmaf(w[k].x, u.x, acc0);
                acc1 = fmaf(w[k].y, u.y, acc1);
                acc0 = fmaf(w[k].z, u.z, acc0);
                acc1 = fmaf(w[k].w, u.w, acc1);
            }
        }
        float acc = acc0 + acc1;
        #pragma unroll
        for (int o = 16; o; o >>= 1) acc += __shfl_down_sync(0xffffffffu, acc, o);
        if (lane == 0) vout[row] = acc + b[row];
    }
}

// ---------------------------------------------------------------------------
__global__ void __launch_bounds__(NTHR, 1)
gl_main(const float* __restrict__ x,   const float* __restrict__ cur,
        const int*   __restrict__ ei,  const float* __restrict__ att,
        const float* __restrict__ W2,  const float* __restrict__ b2,
        const float* __restrict__ W3,  const float* __restrict__ b3,
        const float* __restrict__ Wih, const float* __restrict__ Whh,
        const float* __restrict__ bih, const float* __restrict__ bhh,
        const float* __restrict__ W1,  const float* __restrict__ b1,
        const float* __restrict__ x30, float* __restrict__ out) {
    extern __shared__ float smem[];
    const int lane = threadIdx.x & 31;
    const int warp = threadIdx.x >> 5;

    if (blockIdx.x < NMAT) {
        // ================= matvec / scatter blocks (151, row-cyclic) =========
        float4* sv = (float4*)smem;

        {   // stage v into smem
            const float4* gv = (const float4*)g_v;
            for (int i = threadIdx.x; i < Nn / 4; i += NTHR) sv[i] = gv[i];
        }
        {   // edge scatter
            int tid  = blockIdx.x * NTHR + threadIdx.x;
            int nthr = NMAT * NTHR;
            for (int e = tid; e < Ee; e += nthr) {
                int s = ei[e];
                int d = ei[Ee + e];
                float m = (__ldg(x + s) - __ldg(x + d)) * __ldg(att + e);
                atomicAdd(&g_x1[d], m);
            }
        }
        __syncthreads();

        int gw = blockIdx.x * (NTHR / 32) + warp;
        int nw = NMAT * (NTHR / 32);
        matvec_rows16(W2, sv, b2, g_x21, gw, nw, lane);

        // inter-block spin barrier (proved ~free in R7 comparison)
        __syncthreads();
        if (threadIdx.x == 0) {
            __threadfence();
            atomicAdd(&g_bar1, 1);
            while (atomicAdd(&g_bar1, 0) < NMAT) {}
            __threadfence();
        }
        __syncthreads();

        {   // stage x21 into smem
            const float4* gx = (const float4*)g_x21;
            for (int i = threadIdx.x; i < Nn / 4; i += NTHR) sv[i] = gx[i];
        }
        __syncthreads();

        matvec_rows16(W3, sv, b3, g_x2, gw, nw, lane);

        __syncthreads();
        if (threadIdx.x == 0) {
            __threadfence();
            atomicAdd(&g_done, 1);
        }
    } else {
        // ================= LSTM block: parallel-in-time (R10) =================
        float* s_cur = smem;                        // [2048]
        float* s_h   = smem + 2048;                 // [16384]
        float* bndh0 = smem + 2048 + 16384;         // [520]
        float* bndc0 = bndh0 + BSZ;
        float* bndh1 = bndc0 + BSZ;
        float* bndc1 = bndh1 + BSZ;
        float* s_red = bndc1 + BSZ;                 // [16]
        float* s_x3  = s_red + 16;

        for (int i = threadIdx.x; i < Tt; i += NTHR) s_cur[i] = cur[i];
        for (int i = threadIdx.x; i < BSZ; i += NTHR) {
            bndh0[i] = 0.f; bndc0[i] = 0.f;
            bndh1[i] = 0.f; bndc1[i] = 0.f;
        }
        __syncthreads();

        const int u    = lane & 7;
        const int base = lane & 24;
        const int q    = warp * 4 + (lane >> 3);
        const int t0   = q * STEPS;

        float wi[8], wf[8], wg[8], wo[8];
        #pragma unroll
        for (int j = 0; j < 8; j++) {
            wi[j] = 0.5f * Whh[(u)      * 8 + j];
            wf[j] = 0.5f * Whh[(8 + u)  * 8 + j];
            wg[j] =        Whh[(16 + u) * 8 + j];
            wo[j] = 0.5f * Whh[(24 + u) * 8 + j];
        }
        const float ai = 0.5f * Wih[u],      bi2 = 0.5f * (bih[u]      + bhh[u]);
        const float af = 0.5f * Wih[8 + u],  bf2 = 0.5f * (bih[8 + u]  + bhh[8 + u]);
        const float ag =        Wih[16 + u], bg2 =        (bih[16 + u] + bhh[16 + u]);
        const float ao = 0.5f * Wih[24 + u], bo2 = 0.5f * (bih[24 + u] + bhh[24 + u]);

        #pragma unroll 1
        for (int sweep = 0; sweep < NSWEEP; sweep++) {
            const float* bh_in  = (sweep & 1) ? bndh1 : bndh0;
            const float* bc_in  = (sweep & 1) ? bndc1 : bndc0;
            float* bh_out = (sweep & 1) ? bndh0 : bndh1;
            float* bc_out = (sweep & 1) ? bndc0 : bndc1;

            float h = bh_in[q * 8 + u];
            float c = bc_in[q * 8 + u];

            #pragma unroll 4
            for (int s = 0; s < STEPS; s++) {
                int t = t0 + s;
                float h0 = __shfl_sync(0xffffffffu, h, base + 0);
                float h1 = __shfl_sync(0xffffffffu, h, base + 1);
                float h2 = __shfl_sync(0xffffffffu, h, base + 2);
                float h3 = __shfl_sync(0xffffffffu, h, base + 3);
                float h4 = __shfl_sync(0xffffffffu, h, base + 4);
                float h5 = __shfl_sync(0xffffffffu, h, base + 5);
                float h6 = __shfl_sync(0xffffffffu, h, base + 6);
                float h7 = __shfl_sync(0xffffffffu, h, base + 7);

                float xt = s_cur[t];
                float zi = fmaf(ai, xt, bi2);
                float zf = fmaf(af, xt, bf2);
                float zg = fmaf(ag, xt, bg2);
                float zo = fmaf(ao, xt, bo2);

                zi = fmaf(wi[0], h0, zi); zf = fmaf(wf[0], h0, zf);
                zg = fmaf(wg[0], h0, zg); zo = fmaf(wo[0], h0, zo);
                zi = fmaf(wi[1], h1, zi); zf = fmaf(wf[1], h1, zf);
                zg = fmaf(wg[1], h1, zg); zo = fmaf(wo[1], h1, zo);
                zi = fmaf(wi[2], h2, zi); zf = fmaf(wf[2], h2, zf);
                zg = fmaf(wg[2], h2, zg); zo = fmaf(wo[2], h2, zo);
                zi = fmaf(wi[3], h3, zi); zf = fmaf(wf[3], h3, zf);
                zg = fmaf(wg[3], h3, zg); zo = fmaf(wo[3], h3, zo);
                zi = fmaf(wi[4], h4, zi); zf = fmaf(wf[4], h4, zf);
                zg = fmaf(wg[4], h4, zg); zo = fmaf(wo[4], h4, zo);
                zi = fmaf(wi[5], h5, zi); zf = fmaf(wf[5], h5, zf);
                zg = fmaf(wg[5], h5, zg); zo = fmaf(wo[5], h5, zo);
                zi = fmaf(wi[6], h6, zi); zf = fmaf(wf[6], h6, zf);
                zg = fmaf(wg[6], h6, zg); zo = fmaf(wo[6], h6, zo);
                zi = fmaf(wi[7], h7, zi); zf = fmaf(wf[7], h7, zf);
                zg = fmaf(wg[7], h7, zg); zo = fmaf(wo[7], h7, zo);

                float si = fmaf(tanhap(zi), 0.5f, 0.5f);
                float sf = fmaf(tanhap(zf), 0.5f, 0.5f);
                float tg = tanhap(zg);
                float so = fmaf(tanhap(zo), 0.5f, 0.5f);

                c = fmaf(sf, c, si * tg);
                h = so * tanhap(c);

                s_h[t * 8 + u] = h;
            }

            bh_out[(q + 1) * 8 + u] = h;
            bc_out[(q + 1) * 8 + u] = c;
            __syncthreads();
        }

        // x3 scalar = W1 · hs_flat + b1
        float part = 0.f;
        for (int k = threadIdx.x; k < Tt * 8; k += NTHR)
            part = fmaf(__ldg(W1 + k), s_h[k], part);
        #pragma unroll
        for (int o = 16; o; o >>= 1) part += __shfl_down_sync(0xffffffffu, part, o);
        if (lane == 0) s_red[warp] = part;
        __syncthreads();
        if (threadIdx.x == 0) {
            float s = 0.f;
            #pragma unroll
            for (int w = 0; w < NTHR / 32; w++) s += s_red[w];
            *s_x3 = s + b1[0];
            while (atomicAdd(&g_done, 0) < NMAT) {}
            __threadfence();
        }
        __syncthreads();

        float x3 = *s_x3;
        for (int i = threadIdx.x; i < Nn; i += NTHR)
            out[i] = x[i] + g_x1[i] + g_x2[i] + x3 * x30[i];
    }
}

// ---------------------------------------------------------------------------
extern "C" void kernel_launch(void* const* d_in, const int* in_sizes, int n_in,
                              void* d_out, int out_size) {
    const float* x   = (const float*)d_in[0];
    const float* xTB = (const float*)d_in[1];
    const float* cur = (const float*)d_in[2];
    const int*   ei  = (const int*)  d_in[3];
    const float* att = (const float*)d_in[4];
    const float* W2  = (const float*)d_in[5];
    const float* b2  = (const float*)d_in[6];
    const float* W3  = (const float*)d_in[7];
    const float* b3  = (const float*)d_in[8];
    const float* Wih = (const float*)d_in[9];
    const float* Whh = (const float*)d_in[10];
    const float* bih = (const float*)d_in[11];
    const float* bhh = (const float*)d_in[12];
    const float* W1  = (const float*)d_in[13];
    const float* b1  = (const float*)d_in[14];
    const float* x30 = (const float*)d_in[15];
    float* out = (float*)d_out;

    cudaFuncSetAttribute(gl_main, cudaFuncAttributeMaxDynamicSharedMemorySize,
                         SMEM_BYTES);

    gl_init<<<(Nn + 255) / 256, 256>>>(x, xTB);
    gl_main<<<NBLK, NTHR, SMEM_BYTES>>>(x, cur, ei, att, W2, b2, W3, b3,
                                        Wih, Whh, bih, bhh, W1, b1, x30, out);
}

// round 12
// speedup vs baseline: 1.7494x; 1.0449x over previous
#include <cuda_runtime.h>
#include <cstdint>

#define Nn    8192
#define Ee    262144
#define Tt    2048
#define NMAT  151
#define NBLK  (NMAT + 1)  // + 1 LSTM block
#define NTHR  512
#define NWRP  (NMAT * (NTHR / 32))   // 2416 matvec warps
#define NHR   (Nn * 2)               // 16384 half-row work units
#define NCH   64
#define STEPS 32
#define NSWEEP 3

// ---- scratch (device globals; no allocation allowed) ----
__device__ float g_v[Nn];
__device__ float g_x1[Nn];
__device__ float g_x21a[Nn];     // mv1 half-0 partial (+b2)
__device__ float g_x21b[Nn];     // mv1 half-1 partial
__device__ float g_x2a[Nn];      // mv2 half-0 partial (+b3)
__device__ float g_x2b[Nn];      // mv2 half-1 partial
__device__ int   g_bar1;
__device__ int   g_done;

#define BSZ  ((NCH + 1) * 8)
#define SMEM_FLOATS (2048 + 16384 + 4 * BSZ + 17)
#define SMEM_BYTES (SMEM_FLOATS * 4)

__device__ __forceinline__ float tanhap(float x) {
    float y;
    asm("tanh.approx.f32 %0, %1;" : "=f"(y) : "f"(x));
    return y;
}

// ---------------------------------------------------------------------------
__global__ void gl_init(const float* __restrict__ x, const float* __restrict__ xTB) {
    int i = blockIdx.x * blockDim.x + threadIdx.x;
    if (i < Nn) {
        g_v[i]  = xTB[i] - x[i];
        g_x1[i] = 0.f;
    }
    if (i == 0) { g_bar1 = 0; g_done = 0; }
}

// half-row matvec pass: unit = 4096 contiguous floats of one row.
// half 0 writes vout_a[row] (+bias), half 1 writes vout_b[row].
__device__ __forceinline__ void matvec_halfrows(const float* __restrict__ W,
                                                const float4* __restrict__ sv,
                                                const float* __restrict__ bias,
                                                float* __restrict__ vout_a,
                                                float* __restrict__ vout_b,
                                                int gw, int lane) {
    for (int hr = gw; hr < NHR; hr += NWRP) {
        const int row  = hr >> 1;
        const int half = hr & 1;
        const float4* wr = (const float4*)(W + (size_t)row * Nn) + half * 1024 + lane;
        const float4* svh = sv + half * 1024;
        float acc0 = 0.f, acc1 = 0.f;
        #pragma unroll 1
        for (int c = 0; c < 2; ++c) {
            float4 w[16];
            #pragma unroll
            for (int k = 0; k < 16; ++k)
                w[k] = __ldg(wr + (c * 16 + k) * 32);
            #pragma unroll
            for (int k = 0; k < 16; ++k) {
                float4 u = svh[lane + (c * 16 + k) * 32];
                acc0 = fmaf(w[k].x, u.x, acc0);
                acc1 = fmaf(w[k].y, u.y, acc1);
                acc0 = fmaf(w[k].z, u.z, acc0);
                acc1 = fmaf(w[k].w, u.w, acc1);
            }
        }
        float acc = acc0 + acc1;
        #pragma unroll
        for (int o = 16; o; o >>= 1) acc += __shfl_down_sync(0xffffffffu, acc, o);
        if (lane == 0) {
            if (half) vout_b[row] = acc;
            else      vout_a[row] = acc + bias[row];
        }
    }
}

// ---------------------------------------------------------------------------
__global__ void __launch_bounds__(NTHR, 1)
gl_main(const float* __restrict__ x,   const float* __restrict__ cur,
        const int*   __restrict__ ei,  const float* __restrict__ att,
        const float* __restrict__ W2,  const float* __restrict__ b2,
        const float* __restrict__ W3,  const float* __restrict__ b3,
        const float* __restrict__ Wih, const float* __restrict__ Whh,
        const float* __restrict__ bih, const float* __restrict__ bhh,
        const float* __restrict__ W1,  const float* __restrict__ b1,
        const float* __restrict__ x30, float* __restrict__ out) {
    extern __shared__ float smem[];
    const int lane = threadIdx.x & 31;
    const int warp = threadIdx.x >> 5;

    if (blockIdx.x < NMAT) {
        // ================= matvec / scatter blocks (151, half-row units) =====
        float4* sv = (float4*)smem;

        {   // stage v into smem
            const float4* gv = (const float4*)g_v;
            for (int i = threadIdx.x; i < Nn / 4; i += NTHR) sv[i] = gv[i];
        }
        {   // edge scatter
            int tid  = blockIdx.x * NTHR + threadIdx.x;
            int nthr = NMAT * NTHR;
            for (int e = tid; e < Ee; e += nthr) {
                int s = ei[e];
                int d = ei[Ee + e];
                float m = (__ldg(x + s) - __ldg(x + d)) * __ldg(att + e);
                atomicAdd(&g_x1[d], m);
            }
        }
        __syncthreads();

        const int gw = blockIdx.x * (NTHR / 32) + warp;
        matvec_halfrows(W2, sv, b2, g_x21a, g_x21b, gw, lane);

        // inter-block spin barrier (protects g_x21a/b)
        __syncthreads();
        if (threadIdx.x == 0) {
            __threadfence();
            atomicAdd(&g_bar1, 1);
            while (atomicAdd(&g_bar1, 0) < NMAT) {}
            __threadfence();
        }
        __syncthreads();

        {   // stage x21 = x21a + x21b into smem
            const float4* ga = (const float4*)g_x21a;
            const float4* gb = (const float4*)g_x21b;
            for (int i = threadIdx.x; i < Nn / 4; i += NTHR) {
                float4 a = ga[i], b = gb[i];
                sv[i] = make_float4(a.x + b.x, a.y + b.y, a.z + b.z, a.w + b.w);
            }
        }
        __syncthreads();

        matvec_halfrows(W3, sv, b3, g_x2a, g_x2b, gw, lane);

        __syncthreads();
        if (threadIdx.x == 0) {
            __threadfence();
            atomicAdd(&g_done, 1);
        }
    } else {
        // ================= LSTM block: parallel-in-time (R10) =================
        float* s_cur = smem;                        // [2048]
        float* s_h   = smem + 2048;                 // [16384]
        float* bndh0 = smem + 2048 + 16384;         // [520]
        float* bndc0 = bndh0 + BSZ;
        float* bndh1 = bndc0 + BSZ;
        float* bndc1 = bndh1 + BSZ;
        float* s_red = bndc1 + BSZ;                 // [16]
        float* s_x3  = s_red + 16;

        for (int i = threadIdx.x; i < Tt; i += NTHR) s_cur[i] = cur[i];
        for (int i = threadIdx.x; i < BSZ; i += NTHR) {
            bndh0[i] = 0.f; bndc0[i] = 0.f;
            bndh1[i] = 0.f; bndc1[i] = 0.f;
        }
        __syncthreads();

        const int u    = lane & 7;
        const int base = lane & 24;
        const int q    = warp * 4 + (lane >> 3);
        const int t0   = q * STEPS;

        float wi[8], wf[8], wg[8], wo[8];
        #pragma unroll
        for (int j = 0; j < 8; j++) {
            wi[j] = 0.5f * Whh[(u)      * 8 + j];
            wf[j] = 0.5f * Whh[(8 + u)  * 8 + j];
            wg[j] =        Whh[(16 + u) * 8 + j];
            wo[j] = 0.5f * Whh[(24 + u) * 8 + j];
        }
        const float ai = 0.5f * Wih[u],      bi2 = 0.5f * (bih[u]      + bhh[u]);
        const float af = 0.5f * Wih[8 + u],  bf2 = 0.5f * (bih[8 + u]  + bhh[8 + u]);
        const float ag =        Wih[16 + u], bg2 =        (bih[16 + u] + bhh[16 + u]);
        const float ao = 0.5f * Wih[24 + u], bo2 = 0.5f * (bih[24 + u] + bhh[24 + u]);

        #pragma unroll 1
        for (int sweep = 0; sweep < NSWEEP; sweep++) {
            const float* bh_in  = (sweep & 1) ? bndh1 : bndh0;
            const float* bc_in  = (sweep & 1) ? bndc1 : bndc0;
            float* bh_out = (sweep & 1) ? bndh0 : bndh1;
            float* bc_out = (sweep & 1) ? bndc0 : bndc1;

            float h = bh_in[q * 8 + u];
            float c = bc_in[q * 8 + u];

            #pragma unroll 4
            for (int s = 0; s < STEPS; s++) {
                int t = t0 + s;
                float h0 = __shfl_sync(0xffffffffu, h, base + 0);
                float h1 = __shfl_sync(0xffffffffu, h, base + 1);
                float h2 = __shfl_sync(0xffffffffu, h, base + 2);
                float h3 = __shfl_sync(0xffffffffu, h, base + 3);
                float h4 = __shfl_sync(0xffffffffu, h, base + 4);
                float h5 = __shfl_sync(0xffffffffu, h, base + 5);
                float h6 = __shfl_sync(0xffffffffu, h, base + 6);
                float h7 = __shfl_sync(0xffffffffu, h, base + 7);

                float xt = s_cur[t];
                float zi = fmaf(ai, xt, bi2);
                float zf = fmaf(af, xt, bf2);
                float zg = fmaf(ag, xt, bg2);
                float zo = fmaf(ao, xt, bo2);

                zi = fmaf(wi[0], h0, zi); zf = fmaf(wf[0], h0, zf);
                zg = fmaf(wg[0], h0, zg); zo = fmaf(wo[0], h0, zo);
                zi = fmaf(wi[1], h1, zi); zf = fmaf(wf[1], h1, zf);
                zg = fmaf(wg[1], h1, zg); zo = fmaf(wo[1], h1, zo);
                zi = fmaf(wi[2], h2, zi); zf = fmaf(wf[2], h2, zf);
                zg = fmaf(wg[2], h2, zg); zo = fmaf(wo[2], h2, zo);
                zi = fmaf(wi[3], h3, zi); zf = fmaf(wf[3], h3, zf);
                zg = fmaf(wg[3], h3, zg); zo = fmaf(wo[3], h3, zo);
                zi = fmaf(wi[4], h4, zi); zf = fmaf(wf[4], h4, zf);
                zg = fmaf(wg[4], h4, zg); zo = fmaf(wo[4], h4, zo);
                zi = fmaf(wi[5], h5, zi); zf = fmaf(wf[5], h5, zf);
                zg = fmaf(wg[5], h5, zg); zo = fmaf(wo[5], h5, zo);
                zi = fmaf(wi[6], h6, zi); zf = fmaf(wf[6], h6, zf);
                zg = fmaf(wg[6], h6, zg); zo = fmaf(wo[6], h6, zo);
                zi = fmaf(wi[7], h7, zi); zf = fmaf(wf[7], h7, zf);
                zg = fmaf(wg[7], h7, zg); zo = fmaf(wo[7], h7, zo);

                float si = fmaf(tanhap(zi), 0.5f, 0.5f);
                float sf = fmaf(tanhap(zf), 0.5f, 0.5f);
                float tg = tanhap(zg);
                float so = fmaf(tanhap(zo), 0.5f, 0.5f);

                c = fmaf(sf, c, si * tg);
                h = so * tanhap(c);

                s_h[t * 8 + u] = h;
            }

            bh_out[(q + 1) * 8 + u] = h;
            bc_out[(q + 1) * 8 + u] = c;
            __syncthreads();
        }

        // x3 scalar = W1 · hs_flat + b1
        float part = 0.f;
        for (int k = threadIdx.x; k < Tt * 8; k += NTHR)
            part = fmaf(__ldg(W1 + k), s_h[k], part);
        #pragma unroll
        for (int o = 16; o; o >>= 1) part += __shfl_down_sync(0xffffffffu, part, o);
        if (lane == 0) s_red[warp] = part;
        __syncthreads();
        if (threadIdx.x == 0) {
            float s = 0.f;
            #pragma unroll
            for (int w = 0; w < NTHR / 32; w++) s += s_red[w];
            *s_x3 = s + b1[0];
            while (atomicAdd(&g_done, 0) < NMAT) {}
            __threadfence();
        }
        __syncthreads();

        float x3 = *s_x3;
        for (int i = threadIdx.x; i < Nn; i += NTHR)
            out[i] = x[i] + g_x1[i] + (g_x2a[i] + g_x2b[i]) + x3 * x30[i];
    }
}

// ---------------------------------------------------------------------------
extern "C" void kernel_launch(void* const* d_in, const int* in_sizes, int n_in,
                              void* d_out, int out_size) {
    const float* x   = (const float*)d_in[0];
    const float* xTB = (const float*)d_in[1];
    const float* cur = (const float*)d_in[2];
    const int*   ei  = (const int*)  d_in[3];
    const float* att = (const float*)d_in[4];
    const float* W2  = (const float*)d_in[5];
    const float* b2  = (const float*)d_in[6];
    const float* W3  = (const float*)d_in[7];
    const float* b3  = (const float*)d_in[8];
    const float* Wih = (const float*)d_in[9];
    const float* Whh = (const float*)d_in[10];
    const float* bih = (const float*)d_in[11];
    const float* bhh = (const float*)d_in[12];
    const float* W1  = (const float*)d_in[13];
    const float* b1  = (const float*)d_in[14];
    const float* x30 = (const float*)d_in[15];
    float* out = (float*)d_out;

    cudaFuncSetAttribute(gl_main, cudaFuncAttributeMaxDynamicSharedMemorySize,
                         SMEM_BYTES);

    gl_init<<<(Nn + 255) / 256, 256>>>(x, xTB);
    gl_main<<<NBLK, NTHR, SMEM_BYTES>>>(x, cur, ei, att, W2, b2, W3, b3,
                                        Wih, Whh, bih, bhh, W1, b1, x30, out);
}